// round 2
// baseline (speedup 1.0000x reference)
#include <cuda_runtime.h>
#include <cstdint>

// yolo_detect_target: scores[N,80], boxes[N,4]
// score_i = max_c scores[i,c]; keep = cumprod(score >= 0.25)
// out = sum(keep * score) + sum(keep * rowsum(boxes))
//
// Two-pass segmented scheme:
//  pass1: per 256-row segment -> (first local failing row or INT_MAX,
//         sum of (score+boxsum) for rows strictly before the local fail)
//  pass2: global F = min fail; answer = sum of seg_sum[s] for s <= F/256
//         (segments before F's segment provably have no fail; F's segment's
//          sum already excludes rows >= F; later segments contribute 0)

#define NCH 80
#define ROWS_PER_BLOCK 256
#define MAX_SEGS 16384

__device__ float g_seg_sum[MAX_SEGS];
__device__ int   g_seg_fail[MAX_SEGS];

__global__ void __launch_bounds__(256) yolo_pass1(
    const float* __restrict__ post,
    const float* __restrict__ boxes,
    int N)
{
    const float CONF = 0.25f;
    const int tid  = threadIdx.x;
    const int lane = tid & 31;
    const int warp = tid >> 5;
    int row = blockIdx.x * ROWS_PER_BLOCK + tid;

    float mx = 0.0f;
    float bsum = 0.0f;
    if (row < N) {
        const float4* p = reinterpret_cast<const float4*>(post) + (size_t)row * (NCH / 4);
        #pragma unroll
        for (int i = 0; i < NCH / 4; ++i) {
            float4 v = p[i];
            mx = fmaxf(mx, fmaxf(fmaxf(v.x, v.y), fmaxf(v.z, v.w)));
        }
        float4 b = reinterpret_cast<const float4*>(boxes)[row];
        bsum = b.x + b.y + b.z + b.w;
    }

    // First failing row within the block (global row index), or INT_MAX.
    bool fail = (row < N) && (mx < CONF);
    unsigned bal = __ballot_sync(0xffffffffu, fail);

    __shared__ int   s_fail[ROWS_PER_BLOCK / 32];
    __shared__ float s_sum [ROWS_PER_BLOCK / 32];

    if (lane == 0) {
        s_fail[warp] = bal ? (blockIdx.x * ROWS_PER_BLOCK + warp * 32 + (__ffs(bal) - 1))
                           : 0x7fffffff;
    }
    __syncthreads();

    int bf = 0x7fffffff;
    #pragma unroll
    for (int i = 0; i < ROWS_PER_BLOCK / 32; ++i) bf = min(bf, s_fail[i]);

    float val = (row < N && row < bf) ? (mx + bsum) : 0.0f;

    // warp-shuffle sum
    #pragma unroll
    for (int off = 16; off > 0; off >>= 1)
        val += __shfl_down_sync(0xffffffffu, val, off);
    if (lane == 0) s_sum[warp] = val;
    __syncthreads();

    if (warp == 0) {
        float acc = (lane < ROWS_PER_BLOCK / 32) ? s_sum[lane] : 0.0f;
        #pragma unroll
        for (int off = 4; off > 0; off >>= 1)
            acc += __shfl_down_sync(0xffffffffu, acc, off);
        if (lane == 0) {
            g_seg_sum[blockIdx.x]  = acc;
            g_seg_fail[blockIdx.x] = bf;
        }
    }
}

__global__ void __launch_bounds__(1024) yolo_pass2(float* __restrict__ out, int nseg)
{
    __shared__ int   s_min[32];
    __shared__ float s_sum[32];
    const int t    = threadIdx.x;
    const int lane = t & 31;
    const int warp = t >> 5;

    int mn = 0x7fffffff;
    for (int s = t; s < nseg; s += 1024) mn = min(mn, g_seg_fail[s]);
    #pragma unroll
    for (int off = 16; off > 0; off >>= 1)
        mn = min(mn, __shfl_down_sync(0xffffffffu, mn, off));
    if (lane == 0) s_min[warp] = mn;
    __syncthreads();
    if (warp == 0) {
        int m = s_min[lane];
        #pragma unroll
        for (int off = 16; off > 0; off >>= 1)
            m = min(m, __shfl_down_sync(0xffffffffu, m, off));
        if (lane == 0) s_min[0] = m;
    }
    __syncthreads();
    int F = s_min[0];                 // global first failing row (or INT_MAX)
    int failseg = F / ROWS_PER_BLOCK; // segments <= failseg contribute

    float acc = 0.0f;
    for (int s = t; s < nseg; s += 1024)
        if (s <= failseg) acc += g_seg_sum[s];
    #pragma unroll
    for (int off = 16; off > 0; off >>= 1)
        acc += __shfl_down_sync(0xffffffffu, acc, off);
    if (lane == 0) s_sum[warp] = acc;
    __syncthreads();
    if (warp == 0) {
        float a = s_sum[lane];
        #pragma unroll
        for (int off = 16; off > 0; off >>= 1)
            a += __shfl_down_sync(0xffffffffu, a, off);
        if (lane == 0) out[0] = a;
    }
}

extern "C" void kernel_launch(void* const* d_in, const int* in_sizes, int n_in,
                              void* d_out, int out_size)
{
    const float* post  = (const float*)d_in[0];  // [N, 80]
    const float* boxes = (const float*)d_in[1];  // [N, 4]
    int N = in_sizes[0] / NCH;
    int nseg = (N + ROWS_PER_BLOCK - 1) / ROWS_PER_BLOCK;

    yolo_pass1<<<nseg, ROWS_PER_BLOCK>>>(post, boxes, N);
    yolo_pass2<<<1, 1024>>>((float*)d_out, nseg);
}